// round 2
// baseline (speedup 1.0000x reference)
#include <cuda_runtime.h>

// Exact-rounding helpers: immune to -use_fast_math / fmad contraction.
__device__ __forceinline__ float fm(float a, float b) { return __fmul_rn(a, b); }
__device__ __forceinline__ float fa(float a, float b) { return __fadd_rn(a, b); }
__device__ __forceinline__ float fs(float a, float b) { return __fsub_rn(a, b); }
__device__ __forceinline__ float fd(float a, float b) { return __fdiv_rn(a, b); }

// Dynamics derivative, replicating the reference op graph (order + rounding).
// s = [vx,vy,vz, roll,pitch,yaw, wx,wy,wz]
// d = [ax,ay,az, roll_dot,pitch_dot,yaw_dot, wdx,wdy,wdz]
__device__ __forceinline__ void dyn9(
    const float* __restrict__ s,
    float u0, float tx, float ty, float tz,
    float I0, float I1, float I2,
    float g0, float g1, float g2,
    float* __restrict__ d)
{
    float vx = s[0], vy = s[1], vz = s[2];
    float wx = s[6], wy = s[7], wz = s[8];

    float cr = cosf(s[3]), sr = sinf(s[3]);
    float cp = cosf(s[4]), sp = sinf(s[4]);
    float cy = cosf(s[5]), sy = sinf(s[5]);

    // R[:, :, 2]  (thrust column), left-assoc as in reference
    float r2x = fa(fm(fm(cy, sp), cr), fm(sy, sr));   // c_y*s_p*c_r + s_y*s_r
    float r2y = fs(fm(fm(sy, sp), cr), fm(cy, sr));   // s_y*s_p*c_r - c_y*s_r
    float r2z = fm(cp, cr);                           // c_p*c_r

    // v_norm = max(sqrt(vx^2+vy^2+vz^2), 1e-8)
    float n2 = fa(fa(fm(vx, vx), fm(vy, vy)), fm(vz, vz));
    float vn = fmaxf(__fsqrt_rn(n2), 1e-8f);

    // drag = (-K_DRAG * v_norm) * vel ; acc = (thrust + drag + g) / 1.0
    float nk = fm(-0.05f, vn);
    d[0] = fa(fa(fm(r2x, u0), fm(nk, vx)), g0);
    d[1] = fa(fa(fm(r2y, u0), fm(nk, vy)), g1);
    d[2] = fa(fa(fm(r2z, u0), fm(nk, vz)), g2);

    // omega_cross = cross(omega, omega*I);  omega_dot = (tau - cross)/I
    float bx = fm(wx, I0), by = fm(wy, I1), bz = fm(wz, I2);
    float cxv = fs(fm(wy, bz), fm(wz, by));
    float cyv = fs(fm(wz, bx), fm(wx, bz));
    float czv = fs(fm(wx, by), fm(wy, bx));
    d[6] = fd(fs(tx, cxv), I0);
    d[7] = fd(fs(ty, cyv), I1);
    d[8] = fd(fs(tz, czv), I2);

    // attitude kinematics (exact reference associativity, separate divisions)
    float cpit = (fabsf(cp) < 1e-6f) ? 1e-6f : cp;
    float tp   = fd(sp, cpit);
    d[3] = fa(fa(wx, fm(fm(sr, tp), wy)), fm(fm(cr, tp), wz));
    d[4] = fs(fm(cr, wy), fm(sr, wz));
    d[5] = fa(fm(fd(sr, cpit), wy), fm(fd(cr, cpit), wz));
}

__global__ void __launch_bounds__(256)
drone_rk4_kernel(const float4* __restrict__ st4,
                 const float4* __restrict__ u4,
                 const float*  __restrict__ Ip,
                 const float*  __restrict__ gp,
                 float4* __restrict__ out4,
                 int B)
{
    int i = blockIdx.x * blockDim.x + threadIdx.x;
    if (i >= B) return;

    float4 a = st4[3 * i + 0];   // p0 p1 p2 v0
    float4 b = st4[3 * i + 1];   // v1 v2 r  p
    float4 c = st4[3 * i + 2];   // y  w0 w1 w2
    float4 uu = u4[i];           // u0 tau0 tau1 tau2

    float I0 = __ldg(Ip + 0), I1 = __ldg(Ip + 1), I2 = __ldg(Ip + 2);
    float g0 = __ldg(gp + 0), g1 = __ldg(gp + 1), g2 = __ldg(gp + 2);

    float y[9] = { a.w, b.x, b.y,   // vel
                   b.z, b.w, c.x,   // att
                   c.y, c.z, c.w }; // omega

    const float H2 = 0.005f;                  // 0.5*DT
    const float H1 = 0.01f;                   // DT
    const float W6 = (float)(0.01 / 6.0);     // DT/6 rounded to f32

    float k1[9], k2[9], k3[9], k4[9], t[9];

    // ---- k1 ----
    dyn9(y, uu.x, uu.y, uu.z, uu.w, I0, I1, I2, g0, g1, g2, k1);
    #pragma unroll
    for (int j = 0; j < 9; j++) t[j] = fa(y[j], fm(H2, k1[j]));
    float p2x = t[0], p2y = t[1], p2z = t[2];        // k2 position-derivative = vel of stage-2 state

    // ---- k2 ----
    dyn9(t, uu.x, uu.y, uu.z, uu.w, I0, I1, I2, g0, g1, g2, k2);
    #pragma unroll
    for (int j = 0; j < 9; j++) t[j] = fa(y[j], fm(H2, k2[j]));
    float p3x = t[0], p3y = t[1], p3z = t[2];

    // ---- k3 ----
    dyn9(t, uu.x, uu.y, uu.z, uu.w, I0, I1, I2, g0, g1, g2, k3);
    #pragma unroll
    for (int j = 0; j < 9; j++) t[j] = fa(y[j], fm(H1, k3[j]));
    float p4x = t[0], p4y = t[1], p4z = t[2];

    // ---- k4 ----
    dyn9(t, uu.x, uu.y, uu.z, uu.w, I0, I1, I2, g0, g1, g2, k4);

    // acc = ((k1 + 2*k2) + 2*k3) + k4   (reference association)
    float acc[9];
    #pragma unroll
    for (int j = 0; j < 9; j++)
        acc[j] = fa(fa(fa(k1[j], fm(2.0f, k2[j])), fm(2.0f, k3[j])), k4[j]);

    // position accumulator, same association (k1p = y vel)
    float apx = fa(fa(fa(y[0], fm(2.0f, p2x)), fm(2.0f, p3x)), p4x);
    float apy = fa(fa(fa(y[1], fm(2.0f, p2y)), fm(2.0f, p3y)), p4y);
    float apz = fa(fa(fa(y[2], fm(2.0f, p2z)), fm(2.0f, p3z)), p4z);

    // out = state + W6 * acc
    float4 oa, ob, oc;
    oa.x = fa(a.x, fm(W6, apx));
    oa.y = fa(a.y, fm(W6, apy));
    oa.z = fa(a.z, fm(W6, apz));
    oa.w = fa(y[0], fm(W6, acc[0]));
    ob.x = fa(y[1], fm(W6, acc[1]));
    ob.y = fa(y[2], fm(W6, acc[2]));
    ob.z = fa(y[3], fm(W6, acc[3]));
    ob.w = fa(y[4], fm(W6, acc[4]));
    oc.x = fa(y[5], fm(W6, acc[5]));
    oc.y = fa(y[6], fm(W6, acc[6]));
    oc.z = fa(y[7], fm(W6, acc[7]));
    oc.w = fa(y[8], fm(W6, acc[8]));

    out4[3 * i + 0] = oa;
    out4[3 * i + 1] = ob;
    out4[3 * i + 2] = oc;
}

extern "C" void kernel_launch(void* const* d_in, const int* in_sizes, int n_in,
                              void* d_out, int out_size)
{
    const float4* st = (const float4*)d_in[0];
    const float4* u  = (const float4*)d_in[1];
    const float*  I  = (const float*)d_in[2];
    const float*  g  = (const float*)d_in[3];
    float4* out = (float4*)d_out;

    int B = in_sizes[0] / 12;
    int threads = 256;
    int blocks = (B + threads - 1) / threads;
    drone_rk4_kernel<<<blocks, threads>>>(st, u, I, g, out, B);
}

// round 3
// speedup vs baseline: 1.3592x; 1.3592x over previous
#include <cuda_runtime.h>

// Exact-rounding helpers: immune to fmad contraction / fast-math.
__device__ __forceinline__ float fm(float a, float b) { return __fmul_rn(a, b); }
__device__ __forceinline__ float fa(float a, float b) { return __fadd_rn(a, b); }
__device__ __forceinline__ float fs(float a, float b) { return __fsub_rn(a, b); }
__device__ __forceinline__ float fd(float a, float b) { return __fdiv_rn(a, b); }

// Dynamics derivative, replicating the reference op graph (order + rounding).
// s = [vx,vy,vz, roll,pitch,yaw, wx,wy,wz]
// d = [ax,ay,az, roll_dot,pitch_dot,yaw_dot, wdx,wdy,wdz]
__device__ __forceinline__ void dyn9(
    const float* __restrict__ s,
    float u0, float tx, float ty, float tz,
    float I0, float I1, float I2,
    float g0, float g1, float g2,
    float* __restrict__ d)
{
    float vx = s[0], vy = s[1], vz = s[2];
    float wx = s[6], wy = s[7], wz = s[8];

    // One shared range-reduction per angle; libdevice sincosf produces
    // bit-identical results to separate sinf/cosf.
    float sr, cr, sp, cp, sy, cy;
    sincosf(s[3], &sr, &cr);
    sincosf(s[4], &sp, &cp);
    sincosf(s[5], &sy, &cy);

    // R[:, :, 2]  (thrust column), left-assoc as in reference
    float r2x = fa(fm(fm(cy, sp), cr), fm(sy, sr));   // c_y*s_p*c_r + s_y*s_r
    float r2y = fs(fm(fm(sy, sp), cr), fm(cy, sr));   // s_y*s_p*c_r - c_y*s_r
    float r2z = fm(cp, cr);                           // c_p*c_r

    // v_norm = max(sqrt(vx^2+vy^2+vz^2), 1e-8)
    float n2 = fa(fa(fm(vx, vx), fm(vy, vy)), fm(vz, vz));
    float vn = fmaxf(__fsqrt_rn(n2), 1e-8f);

    // drag = (-K_DRAG * v_norm) * vel ; acc = (thrust + drag + g) / 1.0
    float nk = fm(-0.05f, vn);
    d[0] = fa(fa(fm(r2x, u0), fm(nk, vx)), g0);
    d[1] = fa(fa(fm(r2y, u0), fm(nk, vy)), g1);
    d[2] = fa(fa(fm(r2z, u0), fm(nk, vz)), g2);

    // omega_cross = cross(omega, omega*I);  omega_dot = (tau - cross)/I
    float bx = fm(wx, I0), by = fm(wy, I1), bz = fm(wz, I2);
    float cxv = fs(fm(wy, bz), fm(wz, by));
    float cyv = fs(fm(wz, bx), fm(wx, bz));
    float czv = fs(fm(wx, by), fm(wy, bx));
    d[6] = fd(fs(tx, cxv), I0);
    d[7] = fd(fs(ty, cyv), I1);
    d[8] = fd(fs(tz, czv), I2);

    // attitude kinematics (exact reference associativity, separate divisions)
    float cpit = (fabsf(cp) < 1e-6f) ? 1e-6f : cp;
    float tp   = fd(sp, cpit);
    d[3] = fa(fa(wx, fm(fm(sr, tp), wy)), fm(fm(cr, tp), wz));
    d[4] = fs(fm(cr, wy), fm(sr, wz));
    d[5] = fa(fm(fd(sr, cpit), wy), fm(fd(cr, cpit), wz));
}

__global__ void __launch_bounds__(256, 4)
drone_rk4_kernel(const float4* __restrict__ st4,
                 const float4* __restrict__ u4,
                 const float*  __restrict__ Ip,
                 const float*  __restrict__ gp,
                 float4* __restrict__ out4,
                 int B)
{
    int i = blockIdx.x * blockDim.x + threadIdx.x;
    if (i >= B) return;

    float4 a = st4[3 * i + 0];   // p0 p1 p2 v0
    float4 b = st4[3 * i + 1];   // v1 v2 r  p
    float4 c = st4[3 * i + 2];   // y  w0 w1 w2
    float4 uu = u4[i];           // u0 tau0 tau1 tau2

    float I0 = __ldg(Ip + 0), I1 = __ldg(Ip + 1), I2 = __ldg(Ip + 2);
    float g0 = __ldg(gp + 0), g1 = __ldg(gp + 1), g2 = __ldg(gp + 2);

    float y[9] = { a.w, b.x, b.y,   // vel
                   b.z, b.w, c.x,   // att
                   c.y, c.z, c.w }; // omega

    const float H2 = 0.005f;                  // 0.5*DT
    const float H1 = 0.01f;                   // DT
    const float W6 = (float)(0.01 / 6.0);     // DT/6 rounded to f32

    float k[9], t[9], acc[9];
    float apx, apy, apz;   // position accumulator (vel-derivative Simpson sum)

    // ---- k1 ----  acc = k1; t = y + H2*k1
    dyn9(y, uu.x, uu.y, uu.z, uu.w, I0, I1, I2, g0, g1, g2, k);
    #pragma unroll
    for (int j = 0; j < 9; j++) { acc[j] = k[j]; t[j] = fa(y[j], fm(H2, k[j])); }
    // ap = y_vel + 2*t_vel  (left-assoc: (k1p + 2*k2p))
    apx = fa(y[0], fm(2.0f, t[0]));
    apy = fa(y[1], fm(2.0f, t[1]));
    apz = fa(y[2], fm(2.0f, t[2]));

    // ---- k2 ----  acc = acc + 2*k2; t = y + H2*k2
    dyn9(t, uu.x, uu.y, uu.z, uu.w, I0, I1, I2, g0, g1, g2, k);
    #pragma unroll
    for (int j = 0; j < 9; j++) { acc[j] = fa(acc[j], fm(2.0f, k[j])); t[j] = fa(y[j], fm(H2, k[j])); }
    apx = fa(apx, fm(2.0f, t[0]));
    apy = fa(apy, fm(2.0f, t[1]));
    apz = fa(apz, fm(2.0f, t[2]));

    // ---- k3 ----  acc = acc + 2*k3; t = y + H1*k3
    dyn9(t, uu.x, uu.y, uu.z, uu.w, I0, I1, I2, g0, g1, g2, k);
    #pragma unroll
    for (int j = 0; j < 9; j++) { acc[j] = fa(acc[j], fm(2.0f, k[j])); t[j] = fa(y[j], fm(H1, k[j])); }
    apx = fa(apx, t[0]);
    apy = fa(apy, t[1]);
    apz = fa(apz, t[2]);

    // ---- k4 ----  acc = acc + k4
    dyn9(t, uu.x, uu.y, uu.z, uu.w, I0, I1, I2, g0, g1, g2, k);
    #pragma unroll
    for (int j = 0; j < 9; j++) acc[j] = fa(acc[j], k[j]);

    // out = state + W6 * acc
    float4 oa, ob, oc;
    oa.x = fa(a.x, fm(W6, apx));
    oa.y = fa(a.y, fm(W6, apy));
    oa.z = fa(a.z, fm(W6, apz));
    oa.w = fa(y[0], fm(W6, acc[0]));
    ob.x = fa(y[1], fm(W6, acc[1]));
    ob.y = fa(y[2], fm(W6, acc[2]));
    ob.z = fa(y[3], fm(W6, acc[3]));
    ob.w = fa(y[4], fm(W6, acc[4]));
    oc.x = fa(y[5], fm(W6, acc[5]));
    oc.y = fa(y[6], fm(W6, acc[6]));
    oc.z = fa(y[7], fm(W6, acc[7]));
    oc.w = fa(y[8], fm(W6, acc[8]));

    out4[3 * i + 0] = oa;
    out4[3 * i + 1] = ob;
    out4[3 * i + 2] = oc;
}

extern "C" void kernel_launch(void* const* d_in, const int* in_sizes, int n_in,
                              void* d_out, int out_size)
{
    const float4* st = (const float4*)d_in[0];
    const float4* u  = (const float4*)d_in[1];
    const float*  I  = (const float*)d_in[2];
    const float*  g  = (const float*)d_in[3];
    float4* out = (float4*)d_out;

    int B = in_sizes[0] / 12;
    int threads = 256;
    int blocks = (B + threads - 1) / threads;
    drone_rk4_kernel<<<blocks, threads>>>(st, u, I, g, out, B);
}